// round 10
// baseline (speedup 1.0000x reference)
#include <cuda_runtime.h>

#define HH 512
#define WW 512
#define NPIX (HH*WW)
#define BSZ 64
#define PIX_PER_THREAD 8
#define THREADS 256

__global__ __launch_bounds__(THREADS, 7) void uv_transform_kernel(
    const float* __restrict__ depth,
    const float* __restrict__ R0g,
    const float* __restrict__ t0g,
    const float* __restrict__ R1g,
    const float* __restrict__ t1g,
    const float* __restrict__ Kg,
    float* __restrict__ uv_out,
    float* __restrict__ d_out)
{
    const int b = blockIdx.y;
    const int p0 = (blockIdx.x * THREADS + threadIdx.x) * PIX_PER_THREAD;

    // Front-batch BOTH depth loads (MLP=2) before the constant prologue:
    // independent of the constants, their DRAM latency hides the shuffle chain.
    const float* dptr = depth + (size_t)b * NPIX + p0;
    const float4 dep0 = *reinterpret_cast<const float4*>(dptr);
    const float4 dep1 = *reinterpret_cast<const float4*>(dptr + 4);

    // ---- warp-local per-batch constant computation (every warp, no barrier) ----
    // Lane i (i<9) owns matrix entry (c,d) = (i/3, i%3). All 3x3 algebra via
    // warp shuffles; results broadcast to all lanes at the end.
    const int lane = threadIdx.x & 31;
    const int c = (lane / 3) % 3;
    const int d = lane % 3;
    const unsigned FM = 0xFFFFFFFFu;

    float r0v = 0.f, r1v = 0.f, kv = 0.f, t0v = 0.f, t1v = 0.f;
    if (lane < 9) {
        r0v = R0g[b * 9 + lane];
        r1v = R1g[b * 9 + lane];
        kv  = Kg[lane];
    }
    if (lane < 3) {
        t0v = t0g[b * 3 + lane];
        t1v = t1g[b * 3 + lane];
    }

    // M(c,d) = sum_e R0[c,e] * R1[d,e]   (R0 @ R1^T)
    float Mv = 0.f;
    #pragma unroll
    for (int e = 0; e < 3; e++)
        Mv = fmaf(__shfl_sync(FM, r0v, 3 * c + e),
                  __shfl_sync(FM, r1v, 3 * d + e), Mv);

    // A(c,d) = sum_e M[c,e] * K[d,e]     (M @ K^T)
    float Av = 0.f;
    #pragma unroll
    for (int e = 0; e < 3; e++)
        Av = fmaf(__shfl_sync(FM, Mv, 3 * c + e),
                  __shfl_sync(FM, kv, 3 * d + e), Av);

    // cofactor of K at (c,d) via cyclic indexing (sign-correct)
    const int rr1 = (c + 1) % 3, rr2 = (c + 2) % 3;
    const int cc1 = (d + 1) % 3, cc2 = (d + 2) % 3;
    const float cofv =
        __shfl_sync(FM, kv, 3 * rr1 + cc1) * __shfl_sync(FM, kv, 3 * rr2 + cc2)
      - __shfl_sync(FM, kv, 3 * rr1 + cc2) * __shfl_sync(FM, kv, 3 * rr2 + cc1);

    // det = sum_e K[0,e] * cof(0,e)
    float det = 0.f;
    #pragma unroll
    for (int e = 0; e < 3; e++)
        det = fmaf(__shfl_sync(FM, kv, e), __shfl_sync(FM, cofv, e), det);
    const float rdet = 1.0f / det;

    // Ki(c,d) = cof(d,c) / det   (adjugate transpose)
    const float Kiv = __shfl_sync(FM, cofv, 3 * d + c) * rdet;

    // Bv(c,d) = sum_k Ki[k,c] * A[k,d]   (Ki^T @ A)
    float Bv = 0.f;
    #pragma unroll
    for (int k = 0; k < 3; k++)
        Bv = fmaf(__shfl_sync(FM, Kiv, 3 * k + c),
                  __shfl_sync(FM, Av, 3 * k + d), Bv);

    // biasv for lanes 0..2 (d = lane): t1 @ K^T - t0 @ A
    float biasv = 0.f;
    #pragma unroll
    for (int e = 0; e < 3; e++) {
        biasv = fmaf(__shfl_sync(FM, t1v, e),
                     __shfl_sync(FM, kv, 3 * d + e), biasv);
        biasv = fmaf(-__shfl_sync(FM, t0v, e),
                     __shfl_sync(FM, Av, 3 * e + d), biasv);
    }

    // Broadcast the 12 constants to all lanes (no smem, no barrier).
    const float B00 = __shfl_sync(FM, Bv, 0);
    const float B01 = __shfl_sync(FM, Bv, 1);
    const float B02 = __shfl_sync(FM, Bv, 2);
    const float B10 = __shfl_sync(FM, Bv, 3);
    const float B11 = __shfl_sync(FM, Bv, 4);
    const float B12 = __shfl_sync(FM, Bv, 5);
    const float B20 = __shfl_sync(FM, Bv, 6);
    const float B21 = __shfl_sync(FM, Bv, 7);
    const float B22 = __shfl_sync(FM, Bv, 8);
    const float b0  = __shfl_sync(FM, biasv, 0);
    const float b1  = __shfl_sync(FM, biasv, 1);
    const float b2  = __shfl_sync(FM, biasv, 2);

    // 8 consecutive pixels share a row (512 % 8 == 0)
    const float row = (float)(p0 >> 9);
    const float col = (float)(p0 & 511);

    float r0 = fmaf(col, B00, fmaf(row, B10, B20));
    float r1 = fmaf(col, B01, fmaf(row, B11, B21));
    float r2 = fmaf(col, B02, fmaf(row, B12, B22));

    float* uvp = uv_out + ((size_t)b * NPIX + p0) * 2;
    float* ddp = d_out + (size_t)b * NPIX + p0;

    #pragma unroll
    for (int g = 0; g < 2; g++) {
        const float4 dep = g ? dep1 : dep0;
        const float dv[4] = {dep.x, dep.y, dep.z, dep.w};

        float u[4], v[4], dd[4];
        #pragma unroll
        for (int i = 0; i < 4; i++) {
            const float u3 = fmaf(dv[i], r0, b0);
            const float v3 = fmaf(dv[i], r1, b1);
            const float w3 = fmaf(dv[i], r2, b2);
            dd[i] = w3;
            const float rcp = __frcp_rn(fmaxf(w3, 0.0f) + 1e-12f);
            u[i] = u3 * rcp;
            v[i] = v3 * rcp;
            r0 += B00; r1 += B01; r2 += B02;  // advance one column
        }

        // store this 4-pixel group immediately (bounds live registers)
        float4 uvA, uvB, dq;
        uvA.x = u[0]; uvA.y = v[0]; uvA.z = u[1]; uvA.w = v[1];
        uvB.x = u[2]; uvB.y = v[2]; uvB.z = u[3]; uvB.w = v[3];
        dq.x = dd[0]; dq.y = dd[1]; dq.z = dd[2]; dq.w = dd[3];

        *reinterpret_cast<float4*>(uvp + g * 8)     = uvA;
        *reinterpret_cast<float4*>(uvp + g * 8 + 4) = uvB;
        *reinterpret_cast<float4*>(ddp + g * 4)     = dq;
    }
}

extern "C" void kernel_launch(void* const* d_in, const int* in_sizes, int n_in,
                              void* d_out, int out_size)
{
    // metadata order: depth0, R0, t0, R1, t1, K, ray
    const float* depth = (const float*)d_in[0];
    const float* R0    = (const float*)d_in[1];
    const float* t0    = (const float*)d_in[2];
    const float* R1    = (const float*)d_in[3];
    const float* t1    = (const float*)d_in[4];
    const float* K     = (const float*)d_in[5];

    float* uv_out = (float*)d_out;                           // BS*N*2 floats
    float* dd_out = (float*)d_out + (size_t)BSZ * NPIX * 2;  // BS*N floats

    dim3 grid(NPIX / (THREADS * PIX_PER_THREAD), BSZ);
    uv_transform_kernel<<<grid, THREADS>>>(depth, R0, t0, R1, t1, K, uv_out, dd_out);
}

// round 11
// speedup vs baseline: 1.0846x; 1.0846x over previous
#include <cuda_runtime.h>

#define HH 512
#define WW 512
#define NPIX (HH*WW)
#define BSZ 64
#define PIX_PER_THREAD 4
#define THREADS 256

__global__ __launch_bounds__(THREADS, 8) void uv_transform_kernel(
    const float* __restrict__ depth,
    const float* __restrict__ R0g,
    const float* __restrict__ t0g,
    const float* __restrict__ R1g,
    const float* __restrict__ t1g,
    const float* __restrict__ Kg,
    float* __restrict__ uv_out,
    float* __restrict__ d_out)
{
    const int b = blockIdx.y;
    const int p0 = (blockIdx.x * THREADS + threadIdx.x) * PIX_PER_THREAD;

    // Issue the depth load FIRST: independent of the per-batch constants, so
    // its ~600-cycle DRAM latency hides this warp's (short) shuffle pipeline.
    const float4 dep = *reinterpret_cast<const float4*>(depth + (size_t)b * NPIX + p0);

    // ---- warp-local per-batch constant computation (every warp, no barrier) ----
    // K is structurally [[fx,0,cx],[0,fy,cy],[0,0,1]] (see reference _make_K),
    // so inv(K) is closed-form: no cofactor/determinant shuffle work.
    const int lane = threadIdx.x & 31;
    const int c = (lane / 3) % 3;
    const int d = lane % 3;
    const unsigned FM = 0xFFFFFFFFu;

    // Warp-uniform scalar loads (same address across lanes -> broadcast).
    const float fx = Kg[0], cx = Kg[2], fy = Kg[4], cy = Kg[5];
    const float t00 = t0g[b * 3 + 0], t01 = t0g[b * 3 + 1], t02 = t0g[b * 3 + 2];
    const float t10 = t1g[b * 3 + 0], t11 = t1g[b * 3 + 1], t12 = t1g[b * 3 + 2];
    const float rfx = __frcp_rn(fx), rfy = __frcp_rn(fy);

    float r0v = 0.f, r1v = 0.f;
    if (lane < 9) {
        r0v = R0g[b * 9 + lane];
        r1v = R1g[b * 9 + lane];
    }

    // M(c,d) = sum_e R0[c,e] * R1[d,e]   (R0 @ R1^T)  -- 6 shuffles
    float Mv = 0.f;
    #pragma unroll
    for (int e = 0; e < 3; e++)
        Mv = fmaf(__shfl_sync(FM, r0v, 3 * c + e),
                  __shfl_sync(FM, r1v, 3 * d + e), Mv);

    // Row of M for this lane's c  -- 3 shuffles
    const float m0 = __shfl_sync(FM, Mv, 3 * c + 0);
    const float m1 = __shfl_sync(FM, Mv, 3 * c + 1);
    const float m2 = __shfl_sync(FM, Mv, 3 * c + 2);

    // A(c,d) = M[c,:] . K[d,:]  with K rows (fx,0,cx), (0,fy,cy), (0,0,1)
    float Av;
    if (d == 0)      Av = fmaf(m0, fx, m2 * cx);
    else if (d == 1) Av = fmaf(m1, fy, m2 * cy);
    else             Av = m2;

    // Column d of A  -- 3 shuffles (reused for both B and bias)
    const float a0 = __shfl_sync(FM, Av, 0 + d);
    const float a1 = __shfl_sync(FM, Av, 3 + d);
    const float a2 = __shfl_sync(FM, Av, 6 + d);

    // B(c,d) = Ki^T row c . A[:,d], with Ki = [[1/fx,0,-cx/fx],[0,1/fy,-cy/fy],[0,0,1]]
    // Ki^T rows: (1/fx,0,0), (0,1/fy,0), (-cx/fx,-cy/fy,1)
    float Bv;
    if (c == 0)      Bv = a0 * rfx;
    else if (c == 1) Bv = a1 * rfy;
    else             Bv = fmaf(-cx * rfx, a0, fmaf(-cy * rfy, a1, a2));

    // bias(d) = t1 . K[d,:] - t0 . A[:,d]   (valid on lanes 0..2 where d = lane)
    float t1k;
    if (d == 0)      t1k = fmaf(t10, fx, t12 * cx);
    else if (d == 1) t1k = fmaf(t11, fy, t12 * cy);
    else             t1k = t12;
    const float biasv = t1k - fmaf(t00, a0, fmaf(t01, a1, t02 * a2));

    // Broadcast the 12 constants to all lanes (no smem, no barrier) -- 12 shuffles
    const float B00 = __shfl_sync(FM, Bv, 0);
    const float B01 = __shfl_sync(FM, Bv, 1);
    const float B02 = __shfl_sync(FM, Bv, 2);
    const float B10 = __shfl_sync(FM, Bv, 3);
    const float B11 = __shfl_sync(FM, Bv, 4);
    const float B12 = __shfl_sync(FM, Bv, 5);
    const float B20 = __shfl_sync(FM, Bv, 6);
    const float B21 = __shfl_sync(FM, Bv, 7);
    const float B22 = __shfl_sync(FM, Bv, 8);
    const float b0  = __shfl_sync(FM, biasv, 0);
    const float b1  = __shfl_sync(FM, biasv, 1);
    const float b2  = __shfl_sync(FM, biasv, 2);

    const float dv[4] = {dep.x, dep.y, dep.z, dep.w};

    // pixel coords: 4 consecutive pixels share a row (512 % 4 == 0)
    const float row = (float)(p0 >> 9);
    const float col = (float)(p0 & 511);

    float r0 = fmaf(col, B00, fmaf(row, B10, B20));
    float r1 = fmaf(col, B01, fmaf(row, B11, B21));
    float r2 = fmaf(col, B02, fmaf(row, B12, B22));

    float u[4], v[4], dd[4];
    #pragma unroll
    for (int i = 0; i < PIX_PER_THREAD; i++) {
        const float u3 = fmaf(dv[i], r0, b0);
        const float v3 = fmaf(dv[i], r1, b1);
        const float w3 = fmaf(dv[i], r2, b2);
        dd[i] = w3;
        const float rcp = __frcp_rn(fmaxf(w3, 0.0f) + 1e-12f);
        u[i] = u3 * rcp;
        v[i] = v3 * rcp;
        r0 += B00; r1 += B01; r2 += B02;  // advance one column
    }

    // uv: (BS, N, 2) interleaved -> 2x float4 per thread
    const size_t uvbase = ((size_t)b * NPIX + p0) * 2;
    float4 uvA, uvB;
    uvA.x = u[0]; uvA.y = v[0]; uvA.z = u[1]; uvA.w = v[1];
    uvB.x = u[2]; uvB.y = v[2]; uvB.z = u[3]; uvB.w = v[3];
    *reinterpret_cast<float4*>(uv_out + uvbase)     = uvA;
    *reinterpret_cast<float4*>(uv_out + uvbase + 4) = uvB;

    // d: (BS, N, 1) -> 1x float4
    float4 dq;
    dq.x = dd[0]; dq.y = dd[1]; dq.z = dd[2]; dq.w = dd[3];
    *reinterpret_cast<float4*>(d_out + (size_t)b * NPIX + p0) = dq;
}

extern "C" void kernel_launch(void* const* d_in, const int* in_sizes, int n_in,
                              void* d_out, int out_size)
{
    // metadata order: depth0, R0, t0, R1, t1, K, ray
    const float* depth = (const float*)d_in[0];
    const float* R0    = (const float*)d_in[1];
    const float* t0    = (const float*)d_in[2];
    const float* R1    = (const float*)d_in[3];
    const float* t1    = (const float*)d_in[4];
    const float* K     = (const float*)d_in[5];

    float* uv_out = (float*)d_out;                           // BS*N*2 floats
    float* dd_out = (float*)d_out + (size_t)BSZ * NPIX * 2;  // BS*N floats

    dim3 grid(NPIX / (THREADS * PIX_PER_THREAD), BSZ);
    uv_transform_kernel<<<grid, THREADS>>>(depth, R0, t0, R1, t1, K, uv_out, dd_out);
}

// round 12
// speedup vs baseline: 1.1733x; 1.0818x over previous
#include <cuda_runtime.h>

#define HH 512
#define WW 512
#define NPIX (HH*WW)
#define BSZ 64
#define THREADS 256
#define GROUP_STRIDE (THREADS * 4)        // 1024 pixels between a thread's two groups
#define BLOCK_PIX (THREADS * 8)           // 2048 pixels per block

__global__ __launch_bounds__(THREADS, 7) void uv_transform_kernel(
    const float* __restrict__ depth,
    const float* __restrict__ R0g,
    const float* __restrict__ t0g,
    const float* __restrict__ R1g,
    const float* __restrict__ t1g,
    const float* __restrict__ Kg,
    float* __restrict__ uv_out,
    float* __restrict__ d_out)
{
    const int b = blockIdx.y;
    // Two dense 4-pixel groups per thread, GROUP_STRIDE apart. Warp-level
    // footprint per instruction stays dense (lane stride 16B = 512B/warp).
    const int p0 = blockIdx.x * BLOCK_PIX + threadIdx.x * 4;

    // Front-batch BOTH depth loads (MLP=2) before the constant prologue:
    // independent of the constants, their DRAM latency hides the shuffles.
    const float* dptr = depth + (size_t)b * NPIX + p0;
    const float4 dep0 = *reinterpret_cast<const float4*>(dptr);
    const float4 dep1 = *reinterpret_cast<const float4*>(dptr + GROUP_STRIDE);

    // ---- warp-local per-batch constant computation (every warp, no barrier) ----
    // Lane i (i<9) owns matrix entry (c,d) = (i/3, i%3); shuffle algebra (R9 form).
    const int lane = threadIdx.x & 31;
    const int c = (lane / 3) % 3;
    const int d = lane % 3;
    const unsigned FM = 0xFFFFFFFFu;

    float r0v = 0.f, r1v = 0.f, kv = 0.f, t0v = 0.f, t1v = 0.f;
    if (lane < 9) {
        r0v = R0g[b * 9 + lane];
        r1v = R1g[b * 9 + lane];
        kv  = Kg[lane];
    }
    if (lane < 3) {
        t0v = t0g[b * 3 + lane];
        t1v = t1g[b * 3 + lane];
    }

    // M(c,d) = sum_e R0[c,e] * R1[d,e]   (R0 @ R1^T)
    float Mv = 0.f;
    #pragma unroll
    for (int e = 0; e < 3; e++)
        Mv = fmaf(__shfl_sync(FM, r0v, 3 * c + e),
                  __shfl_sync(FM, r1v, 3 * d + e), Mv);

    // A(c,d) = sum_e M[c,e] * K[d,e]     (M @ K^T)
    float Av = 0.f;
    #pragma unroll
    for (int e = 0; e < 3; e++)
        Av = fmaf(__shfl_sync(FM, Mv, 3 * c + e),
                  __shfl_sync(FM, kv, 3 * d + e), Av);

    // cofactor of K at (c,d) via cyclic indexing (sign-correct)
    const int rr1 = (c + 1) % 3, rr2 = (c + 2) % 3;
    const int cc1 = (d + 1) % 3, cc2 = (d + 2) % 3;
    const float cofv =
        __shfl_sync(FM, kv, 3 * rr1 + cc1) * __shfl_sync(FM, kv, 3 * rr2 + cc2)
      - __shfl_sync(FM, kv, 3 * rr1 + cc2) * __shfl_sync(FM, kv, 3 * rr2 + cc1);

    // det = sum_e K[0,e] * cof(0,e)
    float det = 0.f;
    #pragma unroll
    for (int e = 0; e < 3; e++)
        det = fmaf(__shfl_sync(FM, kv, e), __shfl_sync(FM, cofv, e), det);
    const float rdet = 1.0f / det;

    // Ki(c,d) = cof(d,c) / det   (adjugate transpose)
    const float Kiv = __shfl_sync(FM, cofv, 3 * d + c) * rdet;

    // Bv(c,d) = sum_k Ki[k,c] * A[k,d]   (Ki^T @ A)
    float Bv = 0.f;
    #pragma unroll
    for (int k = 0; k < 3; k++)
        Bv = fmaf(__shfl_sync(FM, Kiv, 3 * k + c),
                  __shfl_sync(FM, Av, 3 * k + d), Bv);

    // biasv for lanes 0..2 (d = lane): t1 @ K^T - t0 @ A
    float biasv = 0.f;
    #pragma unroll
    for (int e = 0; e < 3; e++) {
        biasv = fmaf(__shfl_sync(FM, t1v, e),
                     __shfl_sync(FM, kv, 3 * d + e), biasv);
        biasv = fmaf(-__shfl_sync(FM, t0v, e),
                     __shfl_sync(FM, Av, 3 * e + d), biasv);
    }

    // Broadcast the 12 constants to all lanes (no smem, no barrier).
    const float B00 = __shfl_sync(FM, Bv, 0);
    const float B01 = __shfl_sync(FM, Bv, 1);
    const float B02 = __shfl_sync(FM, Bv, 2);
    const float B10 = __shfl_sync(FM, Bv, 3);
    const float B11 = __shfl_sync(FM, Bv, 4);
    const float B12 = __shfl_sync(FM, Bv, 5);
    const float B20 = __shfl_sync(FM, Bv, 6);
    const float B21 = __shfl_sync(FM, Bv, 7);
    const float B22 = __shfl_sync(FM, Bv, 8);
    const float b0  = __shfl_sync(FM, biasv, 0);
    const float b1  = __shfl_sync(FM, biasv, 1);
    const float b2  = __shfl_sync(FM, biasv, 2);

    // pixel coords: 4 consecutive pixels share a row; group 1 sits exactly
    // 2 rows below group 0 (GROUP_STRIDE = 1024 = 2 * 512).
    const float row = (float)(p0 >> 9);
    const float col = (float)(p0 & 511);

    float gr0 = fmaf(col, B00, fmaf(row, B10, B20));
    float gr1 = fmaf(col, B01, fmaf(row, B11, B21));
    float gr2 = fmaf(col, B02, fmaf(row, B12, B22));

    float* uvp = uv_out + ((size_t)b * NPIX + p0) * 2;
    float* ddp = d_out + (size_t)b * NPIX + p0;

    #pragma unroll
    for (int g = 0; g < 2; g++) {
        const float4 dep = g ? dep1 : dep0;
        const float dv[4] = {dep.x, dep.y, dep.z, dep.w};

        float r0 = gr0, r1 = gr1, r2 = gr2;
        float u[4], v[4], dd[4];
        #pragma unroll
        for (int i = 0; i < 4; i++) {
            const float u3 = fmaf(dv[i], r0, b0);
            const float v3 = fmaf(dv[i], r1, b1);
            const float w3 = fmaf(dv[i], r2, b2);
            dd[i] = w3;
            const float rcp = __frcp_rn(fmaxf(w3, 0.0f) + 1e-12f);
            u[i] = u3 * rcp;
            v[i] = v3 * rcp;
            r0 += B00; r1 += B01; r2 += B02;  // advance one column
        }

        float4 uvA, uvB, dq;
        uvA.x = u[0]; uvA.y = v[0]; uvA.z = u[1]; uvA.w = v[1];
        uvB.x = u[2]; uvB.y = v[2]; uvB.z = u[3]; uvB.w = v[3];
        dq.x = dd[0]; dq.y = dd[1]; dq.z = dd[2]; dq.w = dd[3];

        *reinterpret_cast<float4*>(uvp + g * (GROUP_STRIDE * 2))     = uvA;
        *reinterpret_cast<float4*>(uvp + g * (GROUP_STRIDE * 2) + 4) = uvB;
        *reinterpret_cast<float4*>(ddp + g * GROUP_STRIDE)           = dq;

        // advance two rows for group 1
        gr0 += 2.0f * B10; gr1 += 2.0f * B11; gr2 += 2.0f * B12;
    }
}

extern "C" void kernel_launch(void* const* d_in, const int* in_sizes, int n_in,
                              void* d_out, int out_size)
{
    // metadata order: depth0, R0, t0, R1, t1, K, ray
    const float* depth = (const float*)d_in[0];
    const float* R0    = (const float*)d_in[1];
    const float* t0    = (const float*)d_in[2];
    const float* R1    = (const float*)d_in[3];
    const float* t1    = (const float*)d_in[4];
    const float* K     = (const float*)d_in[5];

    float* uv_out = (float*)d_out;                           // BS*N*2 floats
    float* dd_out = (float*)d_out + (size_t)BSZ * NPIX * 2;  // BS*N floats

    dim3 grid(NPIX / BLOCK_PIX, BSZ);
    uv_transform_kernel<<<grid, THREADS>>>(depth, R0, t0, R1, t1, K, uv_out, dd_out);
}